// round 1
// baseline (speedup 1.0000x reference)
#include <cuda_runtime.h>
#include <math.h>

// Problem constants
#define Bc  2
#define Sc  2048
#define Dc  1024
#define Hc  16
#define DKc 64

// Scratch (allocation-free rule: __device__ globals)
__device__ float g_q[(size_t)Bc * Hc * Sc * DKc];     // 16 MB, [B,H,S,DK]
__device__ float g_k[(size_t)Bc * Hc * Sc * DKc];     // 16 MB
__device__ float g_v[(size_t)Bc * Hc * Sc * DKc];     // 16 MB
__device__ float g_ctx[(size_t)Bc * Sc * Dc];         // 16 MB, [B,S,D] concat layout

// ---------------------------------------------------------------------------
// Kernel 1: QKV projections.  out = X @ W^T + b, scattered to [B,H,S,DK].
// M=4096 (b*s), N=1024, K=1024.  128x128x8 tiles, 8x8 per thread.
// gridDim = (N/128=8, M/128=32, 3), 256 threads.
// ---------------------------------------------------------------------------
__global__ __launch_bounds__(256) void proj_qkv_kernel(
    const float* __restrict__ q_in, const float* __restrict__ k_in,
    const float* __restrict__ v_in,
    const float* __restrict__ wq, const float* __restrict__ wk,
    const float* __restrict__ wv,
    const float* __restrict__ bq, const float* __restrict__ bk,
    const float* __restrict__ bv)
{
    const int K = Dc;  // 1024
    __shared__ float As[8][128];
    __shared__ float Bs[8][128];

    const int z = blockIdx.z;
    const float* X    = (z == 0) ? q_in : (z == 1) ? k_in : v_in;
    const float* W    = (z == 0) ? wq   : (z == 1) ? wk   : wv;
    const float* bias = (z == 0) ? bq   : (z == 1) ? bk   : bv;
    float* dst        = (z == 0) ? g_q  : (z == 1) ? g_k  : g_v;

    const int tid = threadIdx.x;
    const int tx = tid & 15;          // 0..15 -> n sub
    const int ty = tid >> 4;          // 0..15 -> m sub
    const int lRow = tid >> 1;        // 0..127
    const int lCol = (tid & 1) * 4;   // 0 or 4

    const float* Ab = X + (size_t)(blockIdx.y * 128) * K;
    const float* Bb = W + (size_t)(blockIdx.x * 128) * K;

    float acc[8][8];
    #pragma unroll
    for (int i = 0; i < 8; i++)
        #pragma unroll
        for (int j = 0; j < 8; j++) acc[i][j] = 0.0f;

    for (int k0 = 0; k0 < K; k0 += 8) {
        float4 a = *(const float4*)(Ab + (size_t)lRow * K + k0 + lCol);
        float4 b = *(const float4*)(Bb + (size_t)lRow * K + k0 + lCol);
        As[lCol + 0][lRow] = a.x; As[lCol + 1][lRow] = a.y;
        As[lCol + 2][lRow] = a.z; As[lCol + 3][lRow] = a.w;
        Bs[lCol + 0][lRow] = b.x; Bs[lCol + 1][lRow] = b.y;
        Bs[lCol + 2][lRow] = b.z; Bs[lCol + 3][lRow] = b.w;
        __syncthreads();
        #pragma unroll
        for (int kk = 0; kk < 8; kk++) {
            float ra[8], rb[8];
            #pragma unroll
            for (int i = 0; i < 8; i++) ra[i] = As[kk][ty * 8 + i];
            #pragma unroll
            for (int j = 0; j < 8; j++) rb[j] = Bs[kk][tx * 8 + j];
            #pragma unroll
            for (int i = 0; i < 8; i++)
                #pragma unroll
                for (int j = 0; j < 8; j++) acc[i][j] += ra[i] * rb[j];
        }
        __syncthreads();
    }

    // Epilogue: scatter to [B,H,S,DK] with bias
    #pragma unroll
    for (int i = 0; i < 8; i++) {
        const int m = blockIdx.y * 128 + ty * 8 + i;
        const int bb = m >> 11;          // m / 2048
        const int s  = m & 2047;
        #pragma unroll
        for (int j = 0; j < 8; j++) {
            const int n = blockIdx.x * 128 + tx * 8 + j;
            const int h = n >> 6;        // n / 64
            const int d = n & 63;
            dst[(((size_t)(bb * Hc + h)) * Sc + s) * DKc + d] = acc[i][j] + bias[n];
        }
    }
}

// ---------------------------------------------------------------------------
// Kernel 2: scores = Q K^T / sqrt(DK) + (1-mask)*finfo.min
// Per (b,h): M=2048(q), N=2048(k), K=64.  Written into weights region of d_out.
// gridDim = (16, 16, B*H=32), 256 threads.
// ---------------------------------------------------------------------------
__global__ __launch_bounds__(256) void scores_kernel(
    const float* __restrict__ mask, float* __restrict__ wts)
{
    const int K = DKc;  // 64
    __shared__ float As[8][128];
    __shared__ float Bs[8][128];

    const int bh = blockIdx.z;
    const int bb = bh / Hc;
    const float* Ab = g_q + (size_t)bh * Sc * DKc + (size_t)(blockIdx.y * 128) * K;
    const float* Bb = g_k + (size_t)bh * Sc * DKc + (size_t)(blockIdx.x * 128) * K;

    const int tid = threadIdx.x;
    const int tx = tid & 15;
    const int ty = tid >> 4;
    const int lRow = tid >> 1;
    const int lCol = (tid & 1) * 4;

    float acc[8][8];
    #pragma unroll
    for (int i = 0; i < 8; i++)
        #pragma unroll
        for (int j = 0; j < 8; j++) acc[i][j] = 0.0f;

    #pragma unroll
    for (int k0 = 0; k0 < 64; k0 += 8) {
        float4 a = *(const float4*)(Ab + (size_t)lRow * K + k0 + lCol);
        float4 b = *(const float4*)(Bb + (size_t)lRow * K + k0 + lCol);
        As[lCol + 0][lRow] = a.x; As[lCol + 1][lRow] = a.y;
        As[lCol + 2][lRow] = a.z; As[lCol + 3][lRow] = a.w;
        Bs[lCol + 0][lRow] = b.x; Bs[lCol + 1][lRow] = b.y;
        Bs[lCol + 2][lRow] = b.z; Bs[lCol + 3][lRow] = b.w;
        __syncthreads();
        #pragma unroll
        for (int kk = 0; kk < 8; kk++) {
            float ra[8], rb[8];
            #pragma unroll
            for (int i = 0; i < 8; i++) ra[i] = As[kk][ty * 8 + i];
            #pragma unroll
            for (int j = 0; j < 8; j++) rb[j] = Bs[kk][tx * 8 + j];
            #pragma unroll
            for (int i = 0; i < 8; i++)
                #pragma unroll
                for (int j = 0; j < 8; j++) acc[i][j] += ra[i] * rb[j];
        }
        __syncthreads();
    }

    const float scale = 0.125f;  // 1/sqrt(64)
    float* wbase = wts + (size_t)bh * Sc * Sc;
    const float* mbase = mask + (size_t)bb * Sc * Sc;
    #pragma unroll
    for (int i = 0; i < 8; i++) {
        const int mq = blockIdx.y * 128 + ty * 8 + i;
        #pragma unroll
        for (int j = 0; j < 8; j++) {
            const int nk = blockIdx.x * 128 + tx * 8 + j;
            float mk = mbase[(size_t)mq * Sc + nk];
            float v = acc[i][j] * scale + (1.0f - mk) * (-3.402823466e38f);
            wbase[(size_t)mq * Sc + nk] = v;
        }
    }
}

// ---------------------------------------------------------------------------
// Kernel 3: in-place row softmax over [B*H*S, S].  Row held in registers.
// grid = B*H*S = 65536 blocks, 256 threads (8 floats/thread as 2x float4).
// ---------------------------------------------------------------------------
__global__ __launch_bounds__(256) void softmax_kernel(float* __restrict__ w)
{
    float4* p4 = (float4*)(w + (size_t)blockIdx.x * Sc);  // 512 float4 per row
    const int tid = threadIdx.x;

    float4 v0 = p4[tid];
    float4 v1 = p4[tid + 256];

    float m = fmaxf(fmaxf(fmaxf(v0.x, v0.y), fmaxf(v0.z, v0.w)),
                    fmaxf(fmaxf(v1.x, v1.y), fmaxf(v1.z, v1.w)));
    #pragma unroll
    for (int o = 16; o > 0; o >>= 1) m = fmaxf(m, __shfl_xor_sync(0xffffffffu, m, o));

    __shared__ float smax[8];
    __shared__ float ssum[8];
    if ((tid & 31) == 0) smax[tid >> 5] = m;
    __syncthreads();
    float bmax = smax[0];
    #pragma unroll
    for (int i = 1; i < 8; i++) bmax = fmaxf(bmax, smax[i]);

    v0.x = expf(v0.x - bmax); v0.y = expf(v0.y - bmax);
    v0.z = expf(v0.z - bmax); v0.w = expf(v0.w - bmax);
    v1.x = expf(v1.x - bmax); v1.y = expf(v1.y - bmax);
    v1.z = expf(v1.z - bmax); v1.w = expf(v1.w - bmax);

    float s = v0.x + v0.y + v0.z + v0.w + v1.x + v1.y + v1.z + v1.w;
    #pragma unroll
    for (int o = 16; o > 0; o >>= 1) s += __shfl_xor_sync(0xffffffffu, s, o);
    if ((tid & 31) == 0) ssum[tid >> 5] = s;
    __syncthreads();
    float bsum = 0.0f;
    #pragma unroll
    for (int i = 0; i < 8; i++) bsum += ssum[i];

    const float inv = 1.0f / bsum;
    v0.x *= inv; v0.y *= inv; v0.z *= inv; v0.w *= inv;
    v1.x *= inv; v1.y *= inv; v1.z *= inv; v1.w *= inv;
    p4[tid] = v0;
    p4[tid + 256] = v1;
}

// ---------------------------------------------------------------------------
// Kernel 4: ctx = weights @ V, per (b,h): [2048,2048] x [2048,64] -> [2048,64]
// scattered into g_ctx [B,S,D].  128x64x8 tiles, 8x4 per thread.
// gridDim = (1, 16, 32), 256 threads.
// ---------------------------------------------------------------------------
__global__ __launch_bounds__(256) void ctx_kernel(const float* __restrict__ w)
{
    __shared__ float As[8][128];
    __shared__ float Bs[8][64];

    const int bh = blockIdx.z;
    const float* Ab = w + (size_t)bh * Sc * Sc + (size_t)(blockIdx.y * 128) * Sc;
    const float* Vb = g_v + (size_t)bh * Sc * DKc;

    const int tid = threadIdx.x;
    const int tx = tid & 15;          // n sub: tx*4 in 0..60
    const int ty = tid >> 4;          // m sub: ty*8 in 0..120
    const int aRow = tid >> 1;        // 0..127
    const int aCol = (tid & 1) * 4;   // 0 or 4
    const int bRow = tid >> 5;        // 0..7   (k)
    const int bCol = (tid & 31) * 2;  // 0..62  (n)

    float acc[8][4];
    #pragma unroll
    for (int i = 0; i < 8; i++)
        #pragma unroll
        for (int j = 0; j < 4; j++) acc[i][j] = 0.0f;

    for (int k0 = 0; k0 < Sc; k0 += 8) {
        float4 a = *(const float4*)(Ab + (size_t)aRow * Sc + k0 + aCol);
        As[aCol + 0][aRow] = a.x; As[aCol + 1][aRow] = a.y;
        As[aCol + 2][aRow] = a.z; As[aCol + 3][aRow] = a.w;
        float2 bv = *(const float2*)(Vb + (size_t)(k0 + bRow) * DKc + bCol);
        Bs[bRow][bCol] = bv.x; Bs[bRow][bCol + 1] = bv.y;
        __syncthreads();
        #pragma unroll
        for (int kk = 0; kk < 8; kk++) {
            float ra[8], rb[4];
            #pragma unroll
            for (int i = 0; i < 8; i++) ra[i] = As[kk][ty * 8 + i];
            #pragma unroll
            for (int j = 0; j < 4; j++) rb[j] = Bs[kk][tx * 4 + j];
            #pragma unroll
            for (int i = 0; i < 8; i++)
                #pragma unroll
                for (int j = 0; j < 4; j++) acc[i][j] += ra[i] * rb[j];
        }
        __syncthreads();
    }

    const int bb = bh / Hc;
    const int h  = bh % Hc;
    #pragma unroll
    for (int i = 0; i < 8; i++) {
        const int q = blockIdx.y * 128 + ty * 8 + i;
        float* dst = g_ctx + ((size_t)bb * Sc + q) * Dc + h * DKc;
        #pragma unroll
        for (int j = 0; j < 4; j++) {
            dst[tx * 4 + j] = acc[i][j];
        }
    }
}

// ---------------------------------------------------------------------------
// Kernel 5: output projection: out = ctx @ wo^T + bo, [4096,1024]x[1024,1024]
// gridDim = (8, 32), 256 threads.
// ---------------------------------------------------------------------------
__global__ __launch_bounds__(256) void outproj_kernel(
    const float* __restrict__ wo, const float* __restrict__ bo,
    float* __restrict__ out)
{
    const int K = Dc;
    __shared__ float As[8][128];
    __shared__ float Bs[8][128];

    const int tid = threadIdx.x;
    const int tx = tid & 15;
    const int ty = tid >> 4;
    const int lRow = tid >> 1;
    const int lCol = (tid & 1) * 4;

    const float* Ab = g_ctx + (size_t)(blockIdx.y * 128) * K;
    const float* Bb = wo + (size_t)(blockIdx.x * 128) * K;

    float acc[8][8];
    #pragma unroll
    for (int i = 0; i < 8; i++)
        #pragma unroll
        for (int j = 0; j < 8; j++) acc[i][j] = 0.0f;

    for (int k0 = 0; k0 < K; k0 += 8) {
        float4 a = *(const float4*)(Ab + (size_t)lRow * K + k0 + lCol);
        float4 b = *(const float4*)(Bb + (size_t)lRow * K + k0 + lCol);
        As[lCol + 0][lRow] = a.x; As[lCol + 1][lRow] = a.y;
        As[lCol + 2][lRow] = a.z; As[lCol + 3][lRow] = a.w;
        Bs[lCol + 0][lRow] = b.x; Bs[lCol + 1][lRow] = b.y;
        Bs[lCol + 2][lRow] = b.z; Bs[lCol + 3][lRow] = b.w;
        __syncthreads();
        #pragma unroll
        for (int kk = 0; kk < 8; kk++) {
            float ra[8], rb[8];
            #pragma unroll
            for (int i = 0; i < 8; i++) ra[i] = As[kk][ty * 8 + i];
            #pragma unroll
            for (int j = 0; j < 8; j++) rb[j] = Bs[kk][tx * 8 + j];
            #pragma unroll
            for (int i = 0; i < 8; i++)
                #pragma unroll
                for (int j = 0; j < 8; j++) acc[i][j] += ra[i] * rb[j];
        }
        __syncthreads();
    }

    #pragma unroll
    for (int i = 0; i < 8; i++) {
        const int m = blockIdx.y * 128 + ty * 8 + i;
        #pragma unroll
        for (int j = 0; j < 8; j++) {
            const int n = blockIdx.x * 128 + tx * 8 + j;
            out[(size_t)m * Dc + n] = acc[i][j] + bo[n];
        }
    }
}

// ---------------------------------------------------------------------------
// Launch.  Inputs (metadata order = reference signature):
//   0 query [B,S,D]  1 key  2 value  3 mask [B,1,S,S]
//   4 wq  5 bq  6 wk  7 bk  8 wv  9 bv  10 wo  11 bo
// Output buffer = concat(output [B,S,D], attention_weights [B,H,S,S]) fp32.
// ---------------------------------------------------------------------------
extern "C" void kernel_launch(void* const* d_in, const int* in_sizes, int n_in,
                              void* d_out, int out_size)
{
    const float* query = (const float*)d_in[0];
    const float* key   = (const float*)d_in[1];
    const float* value = (const float*)d_in[2];
    const float* mask  = (const float*)d_in[3];
    const float* wq = (const float*)d_in[4];
    const float* bq = (const float*)d_in[5];
    const float* wk = (const float*)d_in[6];
    const float* bk = (const float*)d_in[7];
    const float* wv = (const float*)d_in[8];
    const float* bv = (const float*)d_in[9];
    const float* wo = (const float*)d_in[10];
    const float* bo = (const float*)d_in[11];

    float* out = (float*)d_out;                          // [B,S,D]
    float* wts = out + (size_t)Bc * Sc * Dc;             // [B,H,S,S]

    // 1. QKV projections
    proj_qkv_kernel<<<dim3(Dc / 128, (Bc * Sc) / 128, 3), 256>>>(
        query, key, value, wq, wk, wv, bq, bk, bv);

    // 2. Scores + mask (raw, pre-softmax) into weights region
    scores_kernel<<<dim3(Sc / 128, Sc / 128, Bc * Hc), 256>>>(mask, wts);

    // 3. Row softmax in place -> final attention_weights
    softmax_kernel<<<Bc * Hc * Sc, 256>>>(wts);

    // 4. Context = weights @ V -> concat layout
    ctx_kernel<<<dim3(1, Sc / 128, Bc * Hc), 256>>>(wts);

    // 5. Output projection
    outproj_kernel<<<dim3(Dc / 128, (Bc * Sc) / 128), 256>>>(wo, bo, out);
}

// round 5
// speedup vs baseline: 1.2552x; 1.2552x over previous
#include <cuda_runtime.h>
#include <math.h>
#include <stdint.h>

// Problem constants
#define Bc  2
#define Sc  2048
#define Dc  1024
#define Hc  16
#define DKc 64

#define FMIN_F (-3.402823466e38f)

// Scratch (allocation-free rule: __device__ globals)
__device__ float g_q[(size_t)Bc * Hc * Sc * DKc];     // [B,H,S,DK]
__device__ float g_k[(size_t)Bc * Hc * Sc * DKc];
__device__ float g_v[(size_t)Bc * Hc * Sc * DKc];
__device__ float g_ctx[(size_t)Bc * Sc * Dc];         // [B,S,D] concat layout

// ---------------------------------------------------------------------------
// TF32 helpers
// ---------------------------------------------------------------------------
__device__ __forceinline__ uint32_t f2tf(float x) {
    uint32_t r;
    asm("cvt.rna.tf32.f32 %0, %1;" : "=r"(r) : "f"(x));
    return r;
}

__device__ __forceinline__ void mma_tf32(float* c, const uint32_t* a,
                                         uint32_t b0, uint32_t b1) {
    asm volatile(
        "mma.sync.aligned.m16n8k8.row.col.f32.tf32.tf32.f32 "
        "{%0,%1,%2,%3}, {%4,%5,%6,%7}, {%8,%9}, {%0,%1,%2,%3};"
        : "+f"(c[0]), "+f"(c[1]), "+f"(c[2]), "+f"(c[3])
        : "r"(a[0]), "r"(a[1]), "r"(a[2]), "r"(a[3]), "r"(b0), "r"(b1));
}

// Split-store one fp32 value into hi/lo tf32 planes
#define ST3(Sh, Sl, k, m, x) do {                      \
    uint32_t h_ = f2tf(x);                             \
    (Sh)[k][m] = h_;                                   \
    (Sl)[k][m] = f2tf((x) - __uint_as_float(h_));      \
} while (0)

// ---------------------------------------------------------------------------
// 128x128 3xTF32 GEMM body: C = A[128,K] * B[128,K]^T (both row-major).
// A pre-offset to block row, B pre-offset to block col. 256 threads,
// warps 4x2, warp tile 32x64. Single-buffered SMEM with reg prefetch.
// ---------------------------------------------------------------------------
__device__ __forceinline__ void gemm128x128_3x(
    const float* __restrict__ A, const float* __restrict__ B,
    int K, int lda, int ldb, float (&acc)[2][8][4])
{
    __shared__ uint32_t sAh[16][140], sAl[16][140];
    __shared__ uint32_t sBh[16][140], sBl[16][140];

    const int tid  = threadIdx.x;
    const int lane = tid & 31, wid = tid >> 5;
    const int wm = wid >> 1, wn = wid & 1;
    const int gid = lane >> 2, tig = lane & 3;
    const int r0 = tid >> 2;             // 0..63
    const int c4 = (tid & 3) * 4;        // 0,4,8,12

    #pragma unroll
    for (int mt = 0; mt < 2; mt++)
        #pragma unroll
        for (int nt = 0; nt < 8; nt++)
            #pragma unroll
            for (int j = 0; j < 4; j++) acc[mt][nt][j] = 0.0f;

    const float* Ap = A + (size_t)r0 * lda + c4;
    const float* Bp = B + (size_t)r0 * ldb + c4;
    const size_t a64 = (size_t)64 * lda;
    const size_t b64 = (size_t)64 * ldb;

    float4 va0 = *(const float4*)(Ap);
    float4 va1 = *(const float4*)(Ap + a64);
    float4 vb0 = *(const float4*)(Bp);
    float4 vb1 = *(const float4*)(Bp + b64);

    const int iters = K >> 4;
    for (int it = 0; it < iters; ++it) {
        __syncthreads();   // previous tile's compute done before overwrite
        ST3(sAh, sAl, c4+0, r0, va0.x); ST3(sAh, sAl, c4+1, r0, va0.y);
        ST3(sAh, sAl, c4+2, r0, va0.z); ST3(sAh, sAl, c4+3, r0, va0.w);
        ST3(sAh, sAl, c4+0, r0+64, va1.x); ST3(sAh, sAl, c4+1, r0+64, va1.y);
        ST3(sAh, sAl, c4+2, r0+64, va1.z); ST3(sAh, sAl, c4+3, r0+64, va1.w);
        ST3(sBh, sBl, c4+0, r0, vb0.x); ST3(sBh, sBl, c4+1, r0, vb0.y);
        ST3(sBh, sBl, c4+2, r0, vb0.z); ST3(sBh, sBl, c4+3, r0, vb0.w);
        ST3(sBh, sBl, c4+0, r0+64, vb1.x); ST3(sBh, sBl, c4+1, r0+64, vb1.y);
        ST3(sBh, sBl, c4+2, r0+64, vb1.z); ST3(sBh, sBl, c4+3, r0+64, vb1.w);
        __syncthreads();

        if (it + 1 < iters) {            // prefetch next tile during compute
            const float* An = Ap + (it + 1) * 16;
            const float* Bn = Bp + (it + 1) * 16;
            va0 = *(const float4*)(An);
            va1 = *(const float4*)(An + a64);
            vb0 = *(const float4*)(Bn);
            vb1 = *(const float4*)(Bn + b64);
        }

        #pragma unroll
        for (int ks = 0; ks < 2; ks++) {
            const int kr = ks * 8 + tig;
            uint32_t ah[2][4], al[2][4];
            #pragma unroll
            for (int mt = 0; mt < 2; mt++) {
                const int m0 = wm * 32 + mt * 16;
                ah[mt][0] = sAh[kr    ][m0 + gid];
                ah[mt][1] = sAh[kr    ][m0 + gid + 8];
                ah[mt][2] = sAh[kr + 4][m0 + gid];
                ah[mt][3] = sAh[kr + 4][m0 + gid + 8];
                al[mt][0] = sAl[kr    ][m0 + gid];
                al[mt][1] = sAl[kr    ][m0 + gid + 8];
                al[mt][2] = sAl[kr + 4][m0 + gid];
                al[mt][3] = sAl[kr + 4][m0 + gid + 8];
            }
            #pragma unroll
            for (int nt = 0; nt < 8; nt++) {
                const int n0 = wn * 64 + nt * 8;
                const uint32_t bh0 = sBh[kr    ][n0 + gid];
                const uint32_t bh1 = sBh[kr + 4][n0 + gid];
                const uint32_t bl0 = sBl[kr    ][n0 + gid];
                const uint32_t bl1 = sBl[kr + 4][n0 + gid];
                mma_tf32(acc[0][nt], ah[0], bl0, bl1);
                mma_tf32(acc[0][nt], al[0], bh0, bh1);
                mma_tf32(acc[0][nt], ah[0], bh0, bh1);
                mma_tf32(acc[1][nt], ah[1], bl0, bl1);
                mma_tf32(acc[1][nt], al[1], bh0, bh1);
                mma_tf32(acc[1][nt], ah[1], bh0, bh1);
            }
        }
    }
}

// ---------------------------------------------------------------------------
// 128x64 3xTF32 GEMM body: C = A[128,K] * B[K,64] (A row-major, B k-major).
// 8 warps, warp tile 16x64. Single-buffered.
// ---------------------------------------------------------------------------
__device__ __forceinline__ void gemm128x64_kn_3x(
    const float* __restrict__ A, const float* __restrict__ B,
    int K, int lda, float (&acc)[8][4])
{
    __shared__ uint32_t sAh[16][140], sAl[16][140];
    __shared__ uint32_t sBh[16][76],  sBl[16][76];

    const int tid  = threadIdx.x;
    const int lane = tid & 31, wid = tid >> 5;
    const int gid = lane >> 2, tig = lane & 3;

    const int r0 = tid >> 2;
    const int c4 = (tid & 3) * 4;
    const int kB = tid >> 4;             // 0..15
    const int n4 = (tid & 15) * 4;       // 0..60

    #pragma unroll
    for (int nt = 0; nt < 8; nt++)
        #pragma unroll
        for (int j = 0; j < 4; j++) acc[nt][j] = 0.0f;

    const float* Ap = A + (size_t)r0 * lda + c4;
    const size_t a64 = (size_t)64 * lda;
    const float* Bp = B + (size_t)kB * DKc + n4;

    float4 va0 = *(const float4*)(Ap);
    float4 va1 = *(const float4*)(Ap + a64);
    float4 vb  = *(const float4*)(Bp);

    const int iters = K >> 4;
    for (int it = 0; it < iters; ++it) {
        __syncthreads();
        ST3(sAh, sAl, c4+0, r0, va0.x); ST3(sAh, sAl, c4+1, r0, va0.y);
        ST3(sAh, sAl, c4+2, r0, va0.z); ST3(sAh, sAl, c4+3, r0, va0.w);
        ST3(sAh, sAl, c4+0, r0+64, va1.x); ST3(sAh, sAl, c4+1, r0+64, va1.y);
        ST3(sAh, sAl, c4+2, r0+64, va1.z); ST3(sAh, sAl, c4+3, r0+64, va1.w);
        ST3(sBh, sBl, kB, n4+0, vb.x); ST3(sBh, sBl, kB, n4+1, vb.y);
        ST3(sBh, sBl, kB, n4+2, vb.z); ST3(sBh, sBl, kB, n4+3, vb.w);
        __syncthreads();

        if (it + 1 < iters) {
            const float* An = Ap + (it + 1) * 16;
            const float* Bn = Bp + (size_t)(it + 1) * 16 * DKc;
            va0 = *(const float4*)(An);
            va1 = *(const float4*)(An + a64);
            vb  = *(const float4*)(Bn);
        }

        #pragma unroll
        for (int ks = 0; ks < 2; ks++) {
            const int kr = ks * 8 + tig;
            const int m0 = wid * 16;
            uint32_t ah[4], al[4];
            ah[0] = sAh[kr    ][m0 + gid];
            ah[1] = sAh[kr    ][m0 + gid + 8];
            ah[2] = sAh[kr + 4][m0 + gid];
            ah[3] = sAh[kr + 4][m0 + gid + 8];
            al[0] = sAl[kr    ][m0 + gid];
            al[1] = sAl[kr    ][m0 + gid + 8];
            al[2] = sAl[kr + 4][m0 + gid];
            al[3] = sAl[kr + 4][m0 + gid + 8];
            #pragma unroll
            for (int nt = 0; nt < 8; nt++) {
                const int n0 = nt * 8;
                const uint32_t bh0 = sBh[kr    ][n0 + gid];
                const uint32_t bh1 = sBh[kr + 4][n0 + gid];
                const uint32_t bl0 = sBl[kr    ][n0 + gid];
                const uint32_t bl1 = sBl[kr + 4][n0 + gid];
                mma_tf32(acc[nt], ah, bl0, bl1);
                mma_tf32(acc[nt], al, bh0, bh1);
                mma_tf32(acc[nt], ah, bh0, bh1);
            }
        }
    }
}

// ---------------------------------------------------------------------------
// Kernel 1: QKV projections. grid (8, 32, 3), 256 threads.
// ---------------------------------------------------------------------------
__global__ __launch_bounds__(256) void proj_qkv_tf32(
    const float* __restrict__ q_in, const float* __restrict__ k_in,
    const float* __restrict__ v_in,
    const float* __restrict__ wq, const float* __restrict__ wk,
    const float* __restrict__ wv,
    const float* __restrict__ bq, const float* __restrict__ bk,
    const float* __restrict__ bv)
{
    const int z = blockIdx.z;
    const float* X    = (z == 0) ? q_in : (z == 1) ? k_in : v_in;
    const float* W    = (z == 0) ? wq   : (z == 1) ? wk   : wv;
    const float* bias = (z == 0) ? bq   : (z == 1) ? bk   : bv;
    float* dst        = (z == 0) ? g_q  : (z == 1) ? g_k  : g_v;

    float acc[2][8][4];
    gemm128x128_3x(X + (size_t)blockIdx.y * 128 * Dc,
                   W + (size_t)blockIdx.x * 128 * Dc, Dc, Dc, Dc, acc);

    const int lane = threadIdx.x & 31, wid = threadIdx.x >> 5;
    const int wm = wid >> 1, wn = wid & 1;
    const int gid = lane >> 2, tig = lane & 3;

    auto put = [&](int r, int c, float v) {
        const int b = r >> 11, s = r & 2047, h = c >> 6, d = c & 63;
        dst[(((size_t)(b * Hc + h)) * Sc + s) * DKc + d] = v + bias[c];
    };
    #pragma unroll
    for (int mt = 0; mt < 2; mt++) {
        const int row = blockIdx.y * 128 + wm * 32 + mt * 16 + gid;
        #pragma unroll
        for (int nt = 0; nt < 8; nt++) {
            const int col = blockIdx.x * 128 + wn * 64 + nt * 8 + tig * 2;
            put(row,     col,     acc[mt][nt][0]);
            put(row,     col + 1, acc[mt][nt][1]);
            put(row + 8, col,     acc[mt][nt][2]);
            put(row + 8, col + 1, acc[mt][nt][3]);
        }
    }
}

// ---------------------------------------------------------------------------
// Kernel 2: scores = QK^T/8 + (1-mask)*FMIN. grid (16,16,32).
// ---------------------------------------------------------------------------
__global__ __launch_bounds__(256) void scores_tf32(
    const float* __restrict__ mask, float* __restrict__ wts)
{
    const int bh = blockIdx.z;
    const int b  = bh >> 4;
    const float* Aq = g_q + (size_t)bh * Sc * DKc + (size_t)blockIdx.y * 128 * DKc;
    const float* Bk = g_k + (size_t)bh * Sc * DKc + (size_t)blockIdx.x * 128 * DKc;

    float acc[2][8][4];
    gemm128x128_3x(Aq, Bk, DKc, DKc, DKc, acc);

    const int lane = threadIdx.x & 31, wid = threadIdx.x >> 5;
    const int wm = wid >> 1, wn = wid & 1;
    const int gid = lane >> 2, tig = lane & 3;

    float* wb = wts + (size_t)bh * Sc * Sc;
    const float* mb = mask + (size_t)b * Sc * Sc;

    auto put = [&](int r, int c, float v) {
        const float mk = mb[(size_t)r * Sc + c];
        wb[(size_t)r * Sc + c] = v * 0.125f + (1.0f - mk) * FMIN_F;
    };
    #pragma unroll
    for (int mt = 0; mt < 2; mt++) {
        const int row = blockIdx.y * 128 + wm * 32 + mt * 16 + gid;
        #pragma unroll
        for (int nt = 0; nt < 8; nt++) {
            const int col = blockIdx.x * 128 + wn * 64 + nt * 8 + tig * 2;
            put(row,     col,     acc[mt][nt][0]);
            put(row,     col + 1, acc[mt][nt][1]);
            put(row + 8, col,     acc[mt][nt][2]);
            put(row + 8, col + 1, acc[mt][nt][3]);
        }
    }
}

// ---------------------------------------------------------------------------
// Kernel 3: in-place row softmax.
// ---------------------------------------------------------------------------
__global__ __launch_bounds__(256) void softmax_kernel(float* __restrict__ w)
{
    float4* p4 = (float4*)(w + (size_t)blockIdx.x * Sc);
    const int tid = threadIdx.x;

    float4 v0 = p4[tid];
    float4 v1 = p4[tid + 256];

    float m = fmaxf(fmaxf(fmaxf(v0.x, v0.y), fmaxf(v0.z, v0.w)),
                    fmaxf(fmaxf(v1.x, v1.y), fmaxf(v1.z, v1.w)));
    #pragma unroll
    for (int o = 16; o > 0; o >>= 1) m = fmaxf(m, __shfl_xor_sync(0xffffffffu, m, o));

    __shared__ float smax[8];
    __shared__ float ssum[8];
    if ((tid & 31) == 0) smax[tid >> 5] = m;
    __syncthreads();
    float bmax = smax[0];
    #pragma unroll
    for (int i = 1; i < 8; i++) bmax = fmaxf(bmax, smax[i]);

    v0.x = expf(v0.x - bmax); v0.y = expf(v0.y - bmax);
    v0.z = expf(v0.z - bmax); v0.w = expf(v0.w - bmax);
    v1.x = expf(v1.x - bmax); v1.y = expf(v1.y - bmax);
    v1.z = expf(v1.z - bmax); v1.w = expf(v1.w - bmax);

    float s = v0.x + v0.y + v0.z + v0.w + v1.x + v1.y + v1.z + v1.w;
    #pragma unroll
    for (int o = 16; o > 0; o >>= 1) s += __shfl_xor_sync(0xffffffffu, s, o);
    if ((tid & 31) == 0) ssum[tid >> 5] = s;
    __syncthreads();
    float bsum = 0.0f;
    #pragma unroll
    for (int i = 0; i < 8; i++) bsum += ssum[i];

    const float inv = 1.0f / bsum;
    v0.x *= inv; v0.y *= inv; v0.z *= inv; v0.w *= inv;
    v1.x *= inv; v1.y *= inv; v1.z *= inv; v1.w *= inv;
    p4[tid] = v0;
    p4[tid + 256] = v1;
}

// ---------------------------------------------------------------------------
// Kernel 4: ctx = weights @ V. grid (1, 16, 32).
// ---------------------------------------------------------------------------
__global__ __launch_bounds__(256) void ctx_tf32(const float* __restrict__ wts)
{
    const int bh = blockIdx.z;
    const float* A = wts + (size_t)bh * Sc * Sc + (size_t)blockIdx.y * 128 * Sc;
    const float* V = g_v + (size_t)bh * Sc * DKc;

    float acc[8][4];
    gemm128x64_kn_3x(A, V, Sc, Sc, acc);

    const int lane = threadIdx.x & 31, wid = threadIdx.x >> 5;
    const int gid = lane >> 2, tig = lane & 3;
    const int b = bh >> 4, h = bh & 15;

    const int q0 = blockIdx.y * 128 + wid * 16 + gid;
    #pragma unroll
    for (int nt = 0; nt < 8; nt++) {
        const int col = nt * 8 + tig * 2;
        float* d0 = g_ctx + ((size_t)(b * Sc + q0)) * Dc + h * DKc + col;
        float* d1 = g_ctx + ((size_t)(b * Sc + q0 + 8)) * Dc + h * DKc + col;
        d0[0] = acc[nt][0]; d0[1] = acc[nt][1];
        d1[0] = acc[nt][2]; d1[1] = acc[nt][3];
    }
}

// ---------------------------------------------------------------------------
// Kernel 5: output projection. grid (8, 32).
// ---------------------------------------------------------------------------
__global__ __launch_bounds__(256) void outproj_tf32(
    const float* __restrict__ wo, const float* __restrict__ bo,
    float* __restrict__ out)
{
    float acc[2][8][4];
    gemm128x128_3x(g_ctx + (size_t)blockIdx.y * 128 * Dc,
                   wo + (size_t)blockIdx.x * 128 * Dc, Dc, Dc, Dc, acc);

    const int lane = threadIdx.x & 31, wid = threadIdx.x >> 5;
    const int wm = wid >> 1, wn = wid & 1;
    const int gid = lane >> 2, tig = lane & 3;

    #pragma unroll
    for (int mt = 0; mt < 2; mt++) {
        const int row = blockIdx.y * 128 + wm * 32 + mt * 16 + gid;
        #pragma unroll
        for (int nt = 0; nt < 8; nt++) {
            const int col = blockIdx.x * 128 + wn * 64 + nt * 8 + tig * 2;
            out[(size_t)row * Dc + col]           = acc[mt][nt][0] + bo[col];
            out[(size_t)row * Dc + col + 1]       = acc[mt][nt][1] + bo[col + 1];
            out[(size_t)(row + 8) * Dc + col]     = acc[mt][nt][2] + bo[col];
            out[(size_t)(row + 8) * Dc + col + 1] = acc[mt][nt][3] + bo[col + 1];
        }
    }
}

// ---------------------------------------------------------------------------
// Launch
// ---------------------------------------------------------------------------
extern "C" void kernel_launch(void* const* d_in, const int* in_sizes, int n_in,
                              void* d_out, int out_size)
{
    const float* query = (const float*)d_in[0];
    const float* key   = (const float*)d_in[1];
    const float* value = (const float*)d_in[2];
    const float* mask  = (const float*)d_in[3];
    const float* wq = (const float*)d_in[4];
    const float* bq = (const float*)d_in[5];
    const float* wk = (const float*)d_in[6];
    const float* bk = (const float*)d_in[7];
    const float* wv = (const float*)d_in[8];
    const float* bv = (const float*)d_in[9];
    const float* wo = (const float*)d_in[10];
    const float* bo = (const float*)d_in[11];

    float* out = (float*)d_out;                          // [B,S,D]
    float* wts = out + (size_t)Bc * Sc * Dc;             // [B,H,S,S]

    proj_qkv_tf32<<<dim3(Dc / 128, (Bc * Sc) / 128, 3), 256>>>(
        query, key, value, wq, wk, wv, bq, bk, bv);

    scores_tf32<<<dim3(Sc / 128, Sc / 128, Bc * Hc), 256>>>(mask, wts);

    softmax_kernel<<<Bc * Hc * Sc, 256>>>(wts);

    ctx_tf32<<<dim3(1, Sc / 128, Bc * Hc), 256>>>(wts);

    outproj_tf32<<<dim3(Dc / 128, (Bc * Sc) / 128), 256>>>(wo, bo, out);
}